// round 6
// baseline (speedup 1.0000x reference)
#include <cuda_runtime.h>
#include <cuda_bf16.h>

#define TT    512
#define BN    8192
#define NTOT  (TT * BN)         // 4,194,304
#define NC    32                // time chunks
#define S     (TT / NC)         // 16 steps per chunk
#define Q     (S / 4)           // 4 float4 groups per chunk
#define BLK   256
#define JB    (BN / BLK)        // 32 block-columns
#define GRD   (NC * JB)         // 1024 blocks

#define GAMMA_F 0.99f

// Scratch (device globals: allocation-free)
__device__ float4 g_ratio4[NC * Q * BN / 4 * 4]; // 16 MB, layout [c][q][b]
__device__ float2 g_AB[NC * BN];                 // 4 MB, {A,B} per (c,b)
__device__ float  g_part[2 * GRD];
__device__ unsigned int g_ctr;

// ---------------------------------------------------------------------------
// Pass 1: ratio per element (done bit in sign) + chunk affine (A,B).
// Ascending-time composition:  F_new = F_old o f_t :
//   B = fma(A, Bt, B); A = A*At      (A starts 1, B starts 0)
// ratio packed 4-wide -> one STG.128 per 4 timesteps, coalesced.
// ---------------------------------------------------------------------------
__global__ void __launch_bounds__(BLK)
pass1(const float2* __restrict__ prob,
      const float2* __restrict__ aprob,
      const float*  __restrict__ v,
      const float*  __restrict__ rew,
      const int*    __restrict__ act,
      const int*    __restrict__ dn)
{
    if (blockIdx.x == 0 && threadIdx.x == 0) g_ctr = 0;

    const int c  = blockIdx.x >> 5;
    const int b  = ((blockIdx.x & 31) << 8) + threadIdx.x;
    const int t0 = c * S;

    float A = 1.0f, B = 0.0f;
    float4 rq;

    #pragma unroll
    for (int i = 0; i < S; i++) {
        const int idx = (t0 + i) * BN + b;      // ascending time

        const float2 p  = __ldcs(&prob[idx]);
        const float2 ap = __ldcs(&aprob[idx]);
        const int    a  = __ldcs(&act[idx]);
        const int    d  = __ldcs(&dn[idx]);
        const float  vv = __ldg(&v[idx]);
        const float  rr = __ldg(&rew[idx]);

        const float pa   = a ? p.y  : p.x;
        const float apa  = a ? ap.y : ap.x;
        const float rat  = __fdividef(pa * (ap.x + ap.y), (p.x + p.y) * apa);
        const float g    = d ? 0.0f : GAMMA_F;
        const float rho  = fminf(rat, 1.0f);
        const float At   = rho * g;
        const float Bt   = fmaf(rho, rr - vv, vv);

        B = fmaf(A, Bt, B);                     // compose F o f_t (ascending)
        A = A * At;

        const float packed =
            __uint_as_float(__float_as_uint(rat) | ((unsigned)d << 31));
        if      ((i & 3) == 0) rq.x = packed;
        else if ((i & 3) == 1) rq.y = packed;
        else if ((i & 3) == 2) rq.z = packed;
        else {
            rq.w = packed;
            g_ratio4[(c * Q + (i >> 2)) * BN + b] = rq;  // STG.128 coalesced
        }
    }

    g_AB[c * BN + b] = make_float2(A, B);
}

// ---------------------------------------------------------------------------
// Pass 3: batched-load replay + entry-carry fold + fused finish.
//   1) issue ALL body loads (4x LDG.128 ratio, 16x v, 16x rew) up front
//   2) fold chunk aggregates NC-1..c+1 (float2 LDG.64, unroll 4)
//   3) replay recurrence from registers; reduce
// ---------------------------------------------------------------------------
__global__ void __launch_bounds__(BLK)
pass3(const float*  __restrict__ v,
      const float*  __restrict__ rew,
      const float*  __restrict__ nv,
      float*        __restrict__ out)
{
    const int c  = blockIdx.x >> 5;
    const int b  = ((blockIdx.x & 31) << 8) + threadIdx.x;
    const int t0 = c * S;

    // ---- 1) batch body loads (all independent; high MLP)
    float4 R[Q];
    float  vB[S], rB[S];
    #pragma unroll
    for (int q = 0; q < Q; q++)
        R[q] = __ldcs(&g_ratio4[(c * Q + q) * BN + b]);
    #pragma unroll
    for (int i = 0; i < S; i++) {
        const int idx = (t0 + i) * BN + b;
        vB[i] = __ldg(&v[idx]);
        rB[i] = __ldg(&rew[idx]);
    }

    // ---- 2) entry carry: right-fold over later chunks (fixed order)
    float E = __ldg(&nv[(TT - 1) * BN + b]);
    #pragma unroll 4
    for (int cc = NC - 1; cc > c; cc--) {
        const float2 ab = g_AB[cc * BN + b];
        E = fmaf(ab.x, E, ab.y);
    }

    // ---- 3) replay descending time from registers
    float actor = 0.0f, critic = 0.0f;
    #pragma unroll
    for (int k = 0; k < S; k++) {
        const int i = S - 1 - k;                // descending time
        const float* rp = (const float*)&R[i >> 2];
        const unsigned u = __float_as_uint(rp[i & 3]);
        const float ratio = __uint_as_float(u & 0x7fffffffu);
        const float g    = (u >> 31) ? 0.0f : GAMMA_F;
        const float rho  = fminf(ratio, 1.0f);
        const float adv  = rho * (rB[i] + g * E - vB[i]);
        critic = fmaf(adv, adv, critic);
        const float cl = fminf(fmaxf(ratio, 0.8f), 1.2f);
        actor += fminf(ratio * adv, cl * adv);
        E = vB[i] + adv;
    }

    // ---- deterministic block reduction
    __shared__ float sa[8], sc[8];
    #pragma unroll
    for (int o = 16; o > 0; o >>= 1) {
        actor  += __shfl_down_sync(0xffffffffu, actor,  o);
        critic += __shfl_down_sync(0xffffffffu, critic, o);
    }
    const int w = threadIdx.x >> 5;
    if ((threadIdx.x & 31) == 0) { sa[w] = actor; sc[w] = critic; }
    __syncthreads();
    if (threadIdx.x == 0) {
        float Asum = 0.0f, Csum = 0.0f;
        #pragma unroll
        for (int k = 0; k < 8; k++) { Asum += sa[k]; Csum += sc[k]; }
        g_part[blockIdx.x]       = Asum;
        g_part[GRD + blockIdx.x] = Csum;
    }

    // ---- last block: final deterministic reduction
    __shared__ bool is_last;
    if (threadIdx.x == 0) {
        __threadfence();
        is_last = (atomicAdd(&g_ctr, 1u) == (unsigned)(GRD - 1));
    }
    __syncthreads();
    if (is_last) {
        const int t = threadIdx.x;
        __shared__ float ra[BLK], rc[BLK];
        float Asum = 0.0f, Csum = 0.0f;
        #pragma unroll
        for (int k = 0; k < GRD / BLK; k++) {   // fixed order
            Asum += g_part[t + k * BLK];
            Csum += g_part[GRD + t + k * BLK];
        }
        ra[t] = Asum; rc[t] = Csum;
        __syncthreads();
        #pragma unroll
        for (int s = BLK / 2; s > 0; s >>= 1) {
            if (t < s) { ra[t] += ra[t + s]; rc[t] += rc[t + s]; }
            __syncthreads();
        }
        if (t == 0) {
            const float inv = 1.0f / (float)NTOT;
            out[0] = (-ra[0] + 0.5f * rc[0]) * inv;
        }
    }
}

extern "C" void kernel_launch(void* const* d_in, const int* in_sizes, int n_in,
                              void* d_out, int out_size)
{
    const float2* prob  = (const float2*)d_in[0];
    const float2* aprob = (const float2*)d_in[1];
    const float*  v     = (const float*)d_in[2];
    const float*  nv    = (const float*)d_in[3];
    const float*  rew   = (const float*)d_in[4];
    const int*    act   = (const int*)d_in[5];
    const int*    dn    = (const int*)d_in[6];
    float* out = (float*)d_out;

    pass1<<<GRD, BLK>>>(prob, aprob, v, rew, act, dn);
    pass3<<<GRD, BLK>>>(v, rew, nv, out);
}

// round 7
// speedup vs baseline: 1.0656x; 1.0656x over previous
#include <cuda_runtime.h>
#include <cuda_bf16.h>

#define TT    512
#define BN    8192
#define NTOT  (TT * BN)         // 4,194,304
#define NC    32                // time chunks
#define S     (TT / NC)         // 16 steps per chunk
#define Q     (S / 4)           // 4 ratio-float4 groups per chunk
#define BLK   256
#define JB    (BN / BLK)        // 32 block-columns
#define GRD   (NC * JB)         // 1024 blocks

#define GAMMA_F 0.99f

// Scratch (device globals: allocation-free)
__device__ float4 g_ratio4[NC * Q * BN];   // 16 MB, layout [c][q][b]
__device__ float2 g_AB[NC * BN];           // 4 MB, {A,B} per (c,b) — L2-resident
__device__ float  g_part[2 * GRD];
__device__ unsigned int g_ctr;

// ---------------------------------------------------------------------------
// Pass 1: ratio per element (done bit in sign) + chunk affine map (A,B).
// Ascending-time composition  F <- F o f_t :
//   B = fma(A, Bt, B); A = A * At        (f_t(x) = At*x + Bt)
// ---------------------------------------------------------------------------
__global__ void __launch_bounds__(BLK)
pass1(const float2* __restrict__ prob,
      const float2* __restrict__ aprob,
      const float*  __restrict__ v,
      const float*  __restrict__ rew,
      const int*    __restrict__ act,
      const int*    __restrict__ dn)
{
    if (blockIdx.x == 0 && threadIdx.x == 0) g_ctr = 0;

    const int c  = blockIdx.x >> 5;
    const int b  = ((blockIdx.x & 31) << 8) + threadIdx.x;
    const int t0 = c * S;

    float A = 1.0f, B = 0.0f;
    float4 rq;

    #pragma unroll
    for (int i = 0; i < S; i++) {
        const int idx = (t0 + i) * BN + b;

        const float2 p  = __ldcs(&prob[idx]);
        const float2 ap = __ldcs(&aprob[idx]);
        const int    a  = __ldcs(&act[idx]);
        const int    d  = __ldcs(&dn[idx]);
        const float  vv = __ldg(&v[idx]);
        const float  rr = __ldg(&rew[idx]);

        const float pa   = a ? p.y  : p.x;
        const float apa  = a ? ap.y : ap.x;
        const float rat  = __fdividef(pa * (ap.x + ap.y), (p.x + p.y) * apa);
        const float g    = d ? 0.0f : GAMMA_F;
        const float rho  = fminf(rat, 1.0f);
        const float At   = rho * g;
        const float Bt   = fmaf(rho, rr - vv, vv);

        B = fmaf(A, Bt, B);
        A = A * At;

        const float packed =
            __uint_as_float(__float_as_uint(rat) | ((unsigned)d << 31));
        if      ((i & 3) == 0) rq.x = packed;
        else if ((i & 3) == 1) rq.y = packed;
        else if ((i & 3) == 2) rq.z = packed;
        else {
            rq.w = packed;
            g_ratio4[(c * Q + (i >> 2)) * BN + b] = rq;   // STG.128
        }
    }

    g_AB[c * BN + b] = make_float2(A, B);
}

// ---------------------------------------------------------------------------
// Pass 3: fold + replay + fused finish.
// __launch_bounds__(256, 6): reg cap 42 -> 48 warps/SM (75% occ) guaranteed.
// Batch only the ratio LDG.128s (16 regs); stream v/rew per step.
// ---------------------------------------------------------------------------
__global__ void __launch_bounds__(BLK, 6)
pass3(const float*  __restrict__ v,
      const float*  __restrict__ rew,
      const float*  __restrict__ nv,
      float*        __restrict__ out)
{
    const int c  = blockIdx.x >> 5;
    const int b  = ((blockIdx.x & 31) << 8) + threadIdx.x;
    const int t0 = c * S;

    // ---- batch ratio loads (independent, in flight during the fold)
    float4 R[Q];
    #pragma unroll
    for (int q = 0; q < Q; q++)
        R[q] = __ldcs(&g_ratio4[(c * Q + q) * BN + b]);

    // ---- entry carry: right-fold chunk maps NC-1 .. c+1 (L2-hot, fixed order)
    float E = __ldg(&nv[(TT - 1) * BN + b]);
    #pragma unroll 8
    for (int cc = NC - 1; cc > c; cc--) {
        const float2 ab = g_AB[cc * BN + b];
        E = fmaf(ab.x, E, ab.y);
    }

    // ---- replay descending time; v/rew streamed
    float actor = 0.0f, critic = 0.0f;
    #pragma unroll
    for (int k = 0; k < S; k++) {
        const int i   = S - 1 - k;
        const int idx = (t0 + i) * BN + b;

        const float vv = __ldg(&v[idx]);
        const float rr = __ldg(&rew[idx]);

        const float* rp = (const float*)&R[i >> 2];
        const unsigned u = __float_as_uint(rp[i & 3]);
        const float ratio = __uint_as_float(u & 0x7fffffffu);
        const float g    = (u >> 31) ? 0.0f : GAMMA_F;
        const float rho  = fminf(ratio, 1.0f);
        const float adv  = rho * (rr + g * E - vv);
        critic = fmaf(adv, adv, critic);
        const float cl = fminf(fmaxf(ratio, 0.8f), 1.2f);
        actor += fminf(ratio * adv, cl * adv);
        E = vv + adv;
    }

    // ---- deterministic block reduction
    __shared__ float sa[8], sc[8];
    #pragma unroll
    for (int o = 16; o > 0; o >>= 1) {
        actor  += __shfl_down_sync(0xffffffffu, actor,  o);
        critic += __shfl_down_sync(0xffffffffu, critic, o);
    }
    const int w = threadIdx.x >> 5;
    if ((threadIdx.x & 31) == 0) { sa[w] = actor; sc[w] = critic; }
    __syncthreads();
    if (threadIdx.x == 0) {
        float Asum = 0.0f, Csum = 0.0f;
        #pragma unroll
        for (int k = 0; k < 8; k++) { Asum += sa[k]; Csum += sc[k]; }
        g_part[blockIdx.x]       = Asum;
        g_part[GRD + blockIdx.x] = Csum;
    }

    // ---- last block: final deterministic reduction
    __shared__ bool is_last;
    if (threadIdx.x == 0) {
        __threadfence();
        is_last = (atomicAdd(&g_ctr, 1u) == (unsigned)(GRD - 1));
    }
    __syncthreads();
    if (is_last) {
        const int t = threadIdx.x;
        __shared__ float ra[BLK], rc[BLK];
        float Asum = 0.0f, Csum = 0.0f;
        #pragma unroll
        for (int k = 0; k < GRD / BLK; k++) {    // fixed order
            Asum += g_part[t + k * BLK];
            Csum += g_part[GRD + t + k * BLK];
        }
        ra[t] = Asum; rc[t] = Csum;
        __syncthreads();
        #pragma unroll
        for (int s = BLK / 2; s > 0; s >>= 1) {
            if (t < s) { ra[t] += ra[t + s]; rc[t] += rc[t + s]; }
            __syncthreads();
        }
        if (t == 0) {
            const float inv = 1.0f / (float)NTOT;
            out[0] = (-ra[0] + 0.5f * rc[0]) * inv;
        }
    }
}

extern "C" void kernel_launch(void* const* d_in, const int* in_sizes, int n_in,
                              void* d_out, int out_size)
{
    const float2* prob  = (const float2*)d_in[0];
    const float2* aprob = (const float2*)d_in[1];
    const float*  v     = (const float*)d_in[2];
    const float*  nv    = (const float*)d_in[3];
    const float*  rew   = (const float*)d_in[4];
    const int*    act   = (const int*)d_in[5];
    const int*    dn    = (const int*)d_in[6];
    float* out = (float*)d_out;

    pass1<<<GRD, BLK>>>(prob, aprob, v, rew, act, dn);
    pass3<<<GRD, BLK>>>(v, rew, nv, out);
}